// round 7
// baseline (speedup 1.0000x reference)
#include <cuda_runtime.h>
#include <cuda_bf16.h>
#include <mma.h>
#include <cstdint>

using namespace nvcuda;

#define Bd   32
#define Ld   64
#define Hd   512
#define WDd  300
#define Vd   32000
#define Td   48
#define KX   1324      // 512 + 300 + 512
#define KXP  1328      // padded to x16 (col 1324 = bias via x=1.0)
#define KIH  812       // 512 + 300
#define G3   1536      // 3*H

// split-K geometry
#define SHP  11
#define KCHP 48        // hidproj: 11*48 = 528 >= 512
#define SGH  4
#define KCGH 128       // gh: 4*128 = 512
#define NB_OUT 250     // 32000/128 wmma blocks
#define NB_HP  44      // hidproj: 4 n-blocks * 11 k-slots
#define NB_GH  48      // gh: 12 n-blocks * 4 k-slots

// ---------------- device scratch (static globals; no allocation) ----------------
__device__ __align__(256) __nv_bfloat16 g_Wb[(size_t)Vd * KXP];   // bf16 W_out (+bias col), ~85MB
__device__ __align__(16)  float g_WahT[Hd * Hd];                  // W_a_hid transposed [n][k]
__device__ __align__(16)  float g_encproj[Bd * Ld * Hd];          // enc @ W_a_enc
__device__ __align__(16)  float g_encW[Bd * Ld * G3];             // enc @ W_ih[:,:512]^T  (12.6MB)
__device__ __align__(16)  float g_gxe[Td * Bd * G3];              // emb_t @ W_ih[:,512:]^T (9.4MB)
__device__ __align__(16)  float g_emb[Td * Bd * WDd];
__device__ __align__(16)  float g_hid[2 * Bd * Hd];               // double buffer
__device__ __align__(16)  float g_ghp[SGH * Bd * G3];             // gh split-K partials
__device__ __align__(16)  float g_hpp[SHP * Bd * Hd];             // hidproj split-K partials
__device__ __align__(16)  float g_sc[Bd * Ld];                    // attention scores
__device__ __align__(16)  float g_obuf[Bd * Vd];                  // raw logits scratch (L2-hot)
__device__ __align__(256) __nv_bfloat16 g_xbf[Bd * KXP];          // bf16 [h_new|emb|hid_old|1|0..]

// ---------------- MUFU-free transcendentals (FMA/ALU pipes only) ----------------
__device__ __forceinline__ float fexp_neg(float x) {   // exp(x), x<=0; rel err ~2e-6
    x = fmaxf(x, -87.0f);
    float y = x * 1.44269504088896f;
    float n = rintf(y);
    float f = y - n;
    float p = 1.33335581e-3f;
    p = fmaf(p, f, 9.61812910e-3f);
    p = fmaf(p, f, 5.55041086e-2f);
    p = fmaf(p, f, 2.40226512e-1f);
    p = fmaf(p, f, 6.93147182e-1f);
    p = fmaf(p, f, 1.0f);
    return __int_as_float(((int)n + 127) << 23) * p;
}
__device__ __forceinline__ float frcp12(float d) {     // 1/d, d in [1,2]
    float r = fmaf(-0.5f, d, 1.45710678f);
    r = r * fmaf(-d, r, 2.0f);
    r = r * fmaf(-d, r, 2.0f);
    r = r * fmaf(-d, r, 2.0f);
    return r;
}
__device__ __forceinline__ float ftanh(float x) {
    float ax = fminf(fabsf(x), 9.0f);
    float z = fexp_neg(-2.0f * ax);
    float r = frcp12(1.0f + z);
    float t = fmaf(-2.0f * z, r, 1.0f);
    return copysignf(t, x);
}
__device__ __forceinline__ float fsigm(float x) {
    float ax = fminf(fabsf(x), 30.0f);
    float z = fexp_neg(-ax);
    float r = frcp12(1.0f + z);
    return (x >= 0.f) ? r : z * r;
}

// ---------------- precompute kernels ----------------
__global__ void k_zero_tail(float* __restrict__ out) {
    size_t base = (size_t)Td * Bd * Vd;
    size_t n = (size_t)(Ld - Td) * Bd * Vd;
    size_t i = (size_t)blockIdx.x * blockDim.x + threadIdx.x;
    if (i < n) out[base + i] = 0.f;
}

__global__ void k_convW(const float* __restrict__ W, const float* __restrict__ bout) {
    unsigned i = blockIdx.x * blockDim.x + threadIdx.x;
    unsigned total = (unsigned)Vd * KXP;
    if (i >= total) return;
    unsigned n = i / KXP;
    unsigned k = i - n * KXP;
    float v = (k < KX) ? W[(size_t)n * KX + k] : (k == KX ? bout[n] : 0.f);
    g_Wb[i] = __float2bfloat16(v);
}

__global__ void k_transpWah(const float* __restrict__ W_attn) {
    unsigned i = blockIdx.x * blockDim.x + threadIdx.x;
    if (i >= Hd * Hd) return;
    unsigned n = i / Hd, k = i - n * Hd;
    g_WahT[n * Hd + k] = W_attn[(size_t)(Hd + k) * Hd + n];
}

__global__ void k_gather_emb(const int* __restrict__ targets, const float* __restrict__ embed) {
    unsigned i = blockIdx.x * blockDim.x + threadIdx.x;
    unsigned total = Td * Bd * WDd;
    if (i >= total) return;
    unsigned t = i / (Bd * WDd);
    unsigned r = i - t * (Bd * WDd);
    unsigned b = r / WDd;
    unsigned j = r - b * WDd;
    int tok = (t == 0) ? 1 : targets[b * Td + (t - 1)];
    g_emb[i] = embed[(size_t)tok * WDd + j];
}

__global__ void k_init_hid(const float* __restrict__ ctxv) {
    int i = blockIdx.x * blockDim.x + threadIdx.x;
    if (i < Bd * Hd) g_hid[i] = ctxv[i];
}

__global__ void k_copy_hfinal(float* __restrict__ out) {
    int i = blockIdx.x * blockDim.x + threadIdx.x;
    if (i < Bd * Hd) out[(size_t)Ld * Bd * Vd + i] = g_hid[i];  // h_final in buffer 0
}

// enc_proj = enc(2048x512) @ W_a_enc, element (k,n) of W at W_attn[k*512+n]
__global__ void __launch_bounds__(256) k_encproj(const float* __restrict__ A,
                                                 const float* __restrict__ W_attn)
{
    __shared__ float As[32][33];
    __shared__ float Bs[64][33];
    int tid = threadIdx.x;
    int m0 = blockIdx.y * 32;
    int n0 = blockIdx.x * 64;
    int tm = tid >> 4, tn = tid & 15;
    float acc[2][4];
#pragma unroll
    for (int i = 0; i < 2; i++)
#pragma unroll
        for (int j = 0; j < 4; j++) acc[i][j] = 0.f;

    for (int k0 = 0; k0 < Hd; k0 += 32) {
        {
            int m = tid >> 3, kk = (tid & 7) << 2;
            float4 v = *(const float4*)(A + (size_t)(m0 + m) * Hd + k0 + kk);
            As[m][kk] = v.x; As[m][kk + 1] = v.y; As[m][kk + 2] = v.z; As[m][kk + 3] = v.w;
        }
#pragma unroll
        for (int i = 0; i < 8; i++) {
            int idx = tid + i * 256;
            int kk = idx >> 6;
            int n  = idx & 63;
            Bs[n][kk] = W_attn[(size_t)(k0 + kk) * Hd + n0 + n];
        }
        __syncthreads();
#pragma unroll
        for (int kk = 0; kk < 32; kk++) {
            float a0 = As[tm * 2][kk], a1 = As[tm * 2 + 1][kk];
            float b0 = Bs[tn * 4][kk], b1 = Bs[tn * 4 + 1][kk];
            float b2 = Bs[tn * 4 + 2][kk], b3 = Bs[tn * 4 + 3][kk];
            acc[0][0] += a0 * b0; acc[0][1] += a0 * b1; acc[0][2] += a0 * b2; acc[0][3] += a0 * b3;
            acc[1][0] += a1 * b0; acc[1][1] += a1 * b1; acc[1][2] += a1 * b2; acc[1][3] += a1 * b3;
        }
        __syncthreads();
    }
#pragma unroll
    for (int i = 0; i < 2; i++) {
        int m = m0 + tm * 2 + i;
#pragma unroll
        for (int j = 0; j < 4; j++)
            g_encproj[(size_t)m * Hd + n0 + tn * 4 + j] = acc[i][j];
    }
}

// ---------------- generic SGEMM C[m][n] = sum_k A[m][k]*B[n*ldb+k], 32x64 tiles, K-guarded ----------------
__global__ void __launch_bounds__(256) sgemm_abt(
    const float* __restrict__ A, int lda,
    const float* __restrict__ B, int ldb,
    float* __restrict__ C, int ldc, int K)
{
    __shared__ float As[32][33];
    __shared__ float Bs[64][33];
    int tid = threadIdx.x;
    int m0 = blockIdx.y * 32;
    int n0 = blockIdx.x * 64;
    int tm = tid >> 4, tn = tid & 15;
    float acc[2][4];
#pragma unroll
    for (int i = 0; i < 2; i++)
#pragma unroll
        for (int j = 0; j < 4; j++) acc[i][j] = 0.f;

    for (int k0 = 0; k0 < K; k0 += 32) {
        {
            int m = tid >> 3, kk = (tid & 7) << 2;
            float4 v = make_float4(0.f, 0.f, 0.f, 0.f);
            if (k0 + kk < K)
                v = *(const float4*)(A + (size_t)(m0 + m) * lda + k0 + kk);
            As[m][kk] = v.x; As[m][kk + 1] = v.y; As[m][kk + 2] = v.z; As[m][kk + 3] = v.w;
        }
#pragma unroll
        for (int i = 0; i < 2; i++) {
            int idx = tid + i * 256;
            int n   = idx >> 3;
            int kk  = (idx & 7) << 2;
            float4 v = make_float4(0.f, 0.f, 0.f, 0.f);
            if (k0 + kk < K)
                v = *(const float4*)(B + (size_t)(n0 + n) * ldb + k0 + kk);
            Bs[n][kk] = v.x; Bs[n][kk + 1] = v.y; Bs[n][kk + 2] = v.z; Bs[n][kk + 3] = v.w;
        }
        __syncthreads();
#pragma unroll
        for (int kk = 0; kk < 32; kk++) {
            float a0 = As[tm * 2][kk], a1 = As[tm * 2 + 1][kk];
            float b0 = Bs[tn * 4][kk], b1 = Bs[tn * 4 + 1][kk];
            float b2 = Bs[tn * 4 + 2][kk], b3 = Bs[tn * 4 + 3][kk];
            acc[0][0] += a0 * b0; acc[0][1] += a0 * b1; acc[0][2] += a0 * b2; acc[0][3] += a0 * b3;
            acc[1][0] += a1 * b0; acc[1][1] += a1 * b1; acc[1][2] += a1 * b2; acc[1][3] += a1 * b3;
        }
        __syncthreads();
    }
#pragma unroll
    for (int i = 0; i < 2; i++) {
        int m = m0 + tm * 2 + i;
#pragma unroll
        for (int j = 0; j < 4; j++)
            C[(size_t)m * ldc + n0 + tn * 4 + j] = acc[i][j];
    }
}

// ---------------- M=32 split-K GEMM tile (used for hidproj + gh partials) ----------------
__device__ __forceinline__ void mm32_tile(
    const float* __restrict__ A, int lda,
    const float* __restrict__ B, int ldb,
    int k_beg, int k_end, int n0,
    float* __restrict__ C, int ldc)
{
    __shared__ float As[32][9];
    __shared__ float Bs[8][132];
    int tid = threadIdx.x;
    int tm = tid >> 5;
    int tn = tid & 31;
    float acc[4][4];
#pragma unroll
    for (int i = 0; i < 4; i++)
#pragma unroll
        for (int j = 0; j < 4; j++) acc[i][j] = 0.f;

    for (int k0 = k_beg; k0 < k_end; k0 += 8) {
        {
            int m = tid >> 3, kk = tid & 7;
            int k = k0 + kk;
            As[m][kk] = (k < k_end) ? A[(size_t)m * lda + k] : 0.f;
        }
#pragma unroll
        for (int r = 0; r < 4; r++) {
            int idx = tid + r * 256;
            int n = idx >> 3, kk = idx & 7;
            int k = k0 + kk;
            Bs[kk][n] = (k < k_end) ? B[(size_t)(n0 + n) * ldb + k] : 0.f;
        }
        __syncthreads();
#pragma unroll
        for (int kk = 0; kk < 8; kk++) {
            float a0 = As[tm * 4][kk];
            float a1 = As[tm * 4 + 1][kk];
            float a2 = As[tm * 4 + 2][kk];
            float a3 = As[tm * 4 + 3][kk];
            float4 b = *(const float4*)&Bs[kk][tn * 4];
            acc[0][0] += a0 * b.x; acc[0][1] += a0 * b.y; acc[0][2] += a0 * b.z; acc[0][3] += a0 * b.w;
            acc[1][0] += a1 * b.x; acc[1][1] += a1 * b.y; acc[1][2] += a1 * b.z; acc[1][3] += a1 * b.w;
            acc[2][0] += a2 * b.x; acc[2][1] += a2 * b.y; acc[2][2] += a2 * b.z; acc[2][3] += a2 * b.w;
            acc[3][0] += a3 * b.x; acc[3][1] += a3 * b.y; acc[3][2] += a3 * b.z; acc[3][3] += a3 * b.w;
        }
        __syncthreads();
    }
#pragma unroll
    for (int i = 0; i < 4; i++) {
        float4 v = make_float4(acc[i][0], acc[i][1], acc[i][2], acc[i][3]);
        *(float4*)&C[(size_t)(tm * 4 + i) * ldc + n0 + tn * 4] = v;
    }
}

// hidproj partials: h @ W_a_hid^T  (44 blocks)
__device__ __forceinline__ void hp_block(int e, const float* __restrict__ h) {
    int nbi = e & 3;
    int s = e >> 2;
    int kb = s * KCHP;
    int ke = min(kb + KCHP, Hd);
    mm32_tile(h, Hd, g_WahT, Hd, kb, ke, nbi * 128,
              g_hpp + (size_t)s * Bd * Hd, Hd);
}

// gh partials: h @ W_hh^T  (48 blocks)
__device__ __forceinline__ void gh_block(int e, const float* __restrict__ h,
                                         const float* __restrict__ W_hh) {
    int nbi = e % 12;
    int s = e / 12;
    int kb = s * KCGH;
    mm32_tile(h, Hd, W_hh, Hd, kb, kb + KCGH, nbi * 128,
              g_ghp + (size_t)s * Bd * G3, G3);
}

// prologue: hidproj + gh partials of h0 (92 blocks)
__global__ void __launch_bounds__(256) k_prep0(const float* __restrict__ W_hh) {
    if (blockIdx.x < NB_HP) hp_block(blockIdx.x, g_hid);
    else                    gh_block(blockIdx.x - NB_HP, g_hid, W_hh);
}

// ---------------- attention scores block: 16 l-rows for batch b ----------------
__device__ __forceinline__ void sc_block(int b, int l0,
                                         const float* __restrict__ v_energy,
                                         const float* __restrict__ b_attn)
{
    int tid = threadIdx.x;
    __shared__ float s_hp[Hd];
    __shared__ float s_v[Hd];

    for (int i = tid; i < Hd; i += 256) {
        float hp = b_attn[i];
#pragma unroll
        for (int s = 0; s < SHP; s++) hp += g_hpp[(size_t)s * Bd * Hd + b * Hd + i];
        s_hp[i] = hp;
        s_v[i]  = v_energy[i];
    }
    __syncthreads();

    int w = tid >> 5, lane = tid & 31;
#pragma unroll
    for (int i = 0; i < 2; i++) {
        int l = l0 + w * 2 + i;
        const float* ep = g_encproj + (size_t)(b * Ld + l) * Hd;
        float acc = 0.f;
#pragma unroll 4
        for (int j = lane; j < Hd; j += 32)
            acc += ftanh(ep[j] + s_hp[j]) * s_v[j];
#pragma unroll
        for (int off = 16; off; off >>= 1)
            acc += __shfl_down_sync(0xffffffffu, acc, off);
        if (lane == 0) g_sc[b * Ld + l] = acc;
    }
}

// prologue scores for t=0
__global__ void __launch_bounds__(256) k_attn_sc(const float* __restrict__ v_energy,
                                                 const float* __restrict__ b_attn)
{
    sc_block(blockIdx.x, blockIdx.y * 16, v_energy, b_attn);
}

// ---------------- fused per-step: softmax -> gx_ctx -> GRU gates -> h_new + bf16 x ----------------
__global__ void __launch_bounds__(512) k_step(const float* __restrict__ b_ih,
                                              const float* __restrict__ b_hh,
                                              int t, int cur)
{
    int b = blockIdx.x;
    int tid = threadIdx.x;
    __shared__ float s_sc[Ld];
    __shared__ float s_w[Ld];

    if (tid < Ld) s_sc[tid] = g_sc[b * Ld + tid];
    __syncthreads();
    if (tid < Ld) {
        float m = -1e30f;
#pragma unroll
        for (int l = 0; l < Ld; l++) m = fmaxf(m, s_sc[l]);
        float Z = 0.f;
#pragma unroll
        for (int l = 0; l < Ld; l++) Z += fexp_neg(s_sc[l] - m);
        s_w[tid] = fexp_neg(s_sc[tid] - m) / Z;
    }
    __syncthreads();

    // gx_ctx for the 3 gates of dim tid: n = tid, 512+tid, 1024+tid
    float gxc0 = 0.f, gxc1 = 0.f, gxc2 = 0.f;
    const float* ew = g_encW + (size_t)b * Ld * G3 + tid;
#pragma unroll 4
    for (int l = 0; l < Ld; l++) {
        float wl = s_w[l];
        gxc0 = fmaf(wl, ew[0],      gxc0);
        gxc1 = fmaf(wl, ew[Hd],     gxc1);
        gxc2 = fmaf(wl, ew[2 * Hd], gxc2);
        ew += G3;
    }

    int i = tid;
    const float* ge = g_gxe + (size_t)(t * Bd + b) * G3;
    float gxr = gxc0 + ge[i]          + b_ih[i];
    float gxz = gxc1 + ge[Hd + i]     + b_ih[Hd + i];
    float gxn = gxc2 + ge[2 * Hd + i] + b_ih[2 * Hd + i];

    float ghr = b_hh[i], ghz = b_hh[Hd + i], ghn = b_hh[2 * Hd + i];
#pragma unroll
    for (int s = 0; s < SGH; s++) {
        const float* p = g_ghp + (size_t)s * Bd * G3 + b * G3;
        ghr += p[i]; ghz += p[Hd + i]; ghn += p[2 * Hd + i];
    }

    float r = fsigm(gxr + ghr);
    float z = fsigm(gxz + ghz);
    float n = ftanh(gxn + r * ghn);
    const float* hin = g_hid + cur * (Bd * Hd);
    float* hout      = g_hid + (1 - cur) * (Bd * Hd);
    float ho = hin[b * Hd + i];
    float hn = (1.f - z) * n + z * ho;

    hout[b * Hd + i] = hn;
    g_xbf[b * KXP + i]       = __float2bfloat16(hn);
    g_xbf[b * KXP + KIH + i] = __float2bfloat16(ho);
    if (i < WDd)
        g_xbf[b * KXP + Hd + i] = __float2bfloat16(g_emb[(size_t)(t * Bd + b) * WDd + i]);
    if (i == 0) {
        g_xbf[b * KXP + KX]     = __float2bfloat16(1.0f);  // bias column
        g_xbf[b * KXP + KX + 1] = __float2bfloat16(0.0f);
        g_xbf[b * KXP + KX + 2] = __float2bfloat16(0.0f);
        g_xbf[b * KXP + KX + 3] = __float2bfloat16(0.0f);
    }
}

// ---------------- output GEMM (bf16 wmma, B loaded ONCE) + hidproj/gh partials of h_{t+1} ----------------
// wmma blocks: 8 warps, each owns a 16-col strip and computes BOTH 16-row M-halves
// with a single B fragment -> W_out traffic = 85MB/step (minimum), A is L1-hot.
__global__ void __launch_bounds__(256) k_out_hp(int cur, const float* __restrict__ W_hh)
{
    if (blockIdx.x < NB_OUT) {
        int n0 = blockIdx.x * 128;
        int warp = threadIdx.x >> 5;           // 0..7 -> 16-col strip
        const __nv_bfloat16* aBase = g_xbf;
        const __nv_bfloat16* bBase = g_Wb + (size_t)(n0 + warp * 16) * KXP;

        wmma::fragment<wmma::accumulator, 16, 16, 16, float> acc0, acc1;
        wmma::fill_fragment(acc0, 0.f);
        wmma::fill_fragment(acc1, 0.f);

        for (int k0 = 0; k0 < KXP; k0 += 16) {
            wmma::fragment<wmma::matrix_b, 16, 16, 16, __nv_bfloat16, wmma::col_major> b;
            wmma::load_matrix_sync(b, bBase + k0, KXP);
            wmma::fragment<wmma::matrix_a, 16, 16, 16, __nv_bfloat16, wmma::row_major> a0, a1;
            wmma::load_matrix_sync(a0, aBase + k0, KXP);
            wmma::load_matrix_sync(a1, aBase + (size_t)16 * KXP + k0, KXP);
            wmma::mma_sync(acc0, a0, b, acc0);
            wmma::mma_sync(acc1, a1, b, acc1);
        }
        float* cp = g_obuf + n0 + warp * 16;
        wmma::store_matrix_sync(cp,                     acc0, Vd, wmma::mem_row_major);
        wmma::store_matrix_sync(cp + (size_t)16 * Vd,   acc1, Vd, wmma::mem_row_major);
    } else if (blockIdx.x < NB_OUT + NB_HP) {
        hp_block(blockIdx.x - NB_OUT, g_hid + (1 - cur) * (Bd * Hd));
    } else {
        gh_block(blockIdx.x - NB_OUT - NB_HP, g_hid + (1 - cur) * (Bd * Hd), W_hh);
    }
}

// ---------------- fused: lse+write(t) || scores(t+1) ----------------
__global__ void __launch_bounds__(256) k_lse_sc(float* __restrict__ out, int t,
                                                const float* __restrict__ v_energy,
                                                const float* __restrict__ b_attn)
{
    if (blockIdx.x >= Bd) {
        int e = blockIdx.x - Bd;
        sc_block(e >> 2, (e & 3) * 16, v_energy, b_attn);
        return;
    }
    int b = blockIdx.x;
    int tid = threadIdx.x;
    const float* row = g_obuf + (size_t)b * Vd;
    float* orow = out + ((size_t)t * Bd + b) * Vd;
    __shared__ float sm[256], ss[256];

    // online max+sumexp in one deterministic pass
    float m = -1e30f, s = 0.f;
    for (int v = tid; v < Vd; v += 256) {
        float x = row[v];
        if (x > m) { s = fmaf(s, fexp_neg(m - x), 1.f); m = x; }
        else       { s += fexp_neg(x - m); }
    }
    sm[tid] = m; ss[tid] = s;
    __syncthreads();
    for (int off = 128; off; off >>= 1) {
        if (tid < off) {
            float m2 = sm[tid + off], s2 = ss[tid + off];
            float M = fmaxf(sm[tid], m2);
            ss[tid] = ss[tid] * fexp_neg(sm[tid] - M) + s2 * fexp_neg(m2 - M);
            sm[tid] = M;
        }
        __syncthreads();
    }
    float lse = sm[0] + logf(ss[0]);

    for (int v = tid; v < Vd; v += 256)
        orow[v] = row[v] - lse;
}

// ---------------- host launcher (graph-capturable; all default-stream) ----------------
extern "C" void kernel_launch(void* const* d_in, const int* in_sizes, int n_in,
                              void* d_out, int out_size)
{
    const float* enc      = (const float*)d_in[0];
    const float* ctxv     = (const float*)d_in[1];
    const int*   targets  = (const int*)  d_in[2];
    const float* embed    = (const float*)d_in[3];
    const float* W_attn   = (const float*)d_in[4];
    const float* b_attn   = (const float*)d_in[5];
    const float* v_energy = (const float*)d_in[6];
    const float* W_ih     = (const float*)d_in[7];
    const float* W_hh     = (const float*)d_in[8];
    const float* b_ih     = (const float*)d_in[9];
    const float* b_hh     = (const float*)d_in[10];
    const float* W_out    = (const float*)d_in[11];
    const float* b_out    = (const float*)d_in[12];
    float* out = (float*)d_out;

    float *p_encW, *p_gxe, *p_emb;
    cudaGetSymbolAddress((void**)&p_encW, g_encW);
    cudaGetSymbolAddress((void**)&p_gxe,  g_gxe);
    cudaGetSymbolAddress((void**)&p_emb,  g_emb);

    // ---- precompute ----
    {
        size_t n = (size_t)(Ld - Td) * Bd * Vd;
        k_zero_tail<<<(unsigned)((n + 255) / 256), 256>>>(out);
    }
    {
        unsigned total = (unsigned)Vd * KXP;
        k_convW<<<(total + 255) / 256, 256>>>(W_out, b_out);
    }
    k_transpWah<<<(Hd * Hd + 255) / 256, 256>>>(W_attn);
    {
        unsigned total = Td * Bd * WDd;
        k_gather_emb<<<(total + 255) / 256, 256>>>(targets, embed);
    }
    k_init_hid<<<(Bd * Hd + 255) / 256, 256>>>(ctxv);
    k_encproj<<<dim3(Hd / 64, (Bd * Ld) / 32), 256>>>(enc, W_attn);
    // encW = enc @ W_ih[:, :512]^T   (2048 x 1536, K=512)
    sgemm_abt<<<dim3(G3 / 64, (Bd * Ld) / 32), 256>>>(enc, Hd, W_ih, KIH, p_encW, G3, Hd);
    // gx_emb = emb_all @ W_ih[:, 512:812]^T   (1536 x 1536, K=300)
    sgemm_abt<<<dim3(G3 / 64, (Td * Bd) / 32), 256>>>(p_emb, WDd, W_ih + Hd, KIH, p_gxe, G3, WDd);
    k_prep0<<<NB_HP + NB_GH, 256>>>(W_hh);             // hidproj + gh partials of h0
    k_attn_sc<<<dim3(Bd, 4), 256>>>(v_energy, b_attn); // scores for t=0

    // ---- 48 decode steps, 3 launches each ----
    for (int t = 0; t < Td; t++) {
        int cur = t & 1;
        k_step<<<Bd, 512>>>(b_ih, b_hh, t, cur);
        k_out_hp<<<NB_OUT + NB_HP + NB_GH, 256>>>(cur, W_hh);
        k_lse_sc<<<Bd + Bd * 4, 256>>>(out, t, v_energy, b_attn);
    }

    k_copy_hfinal<<<(Bd * Hd + 255) / 256, 256>>>(out);
    (void)in_sizes; (void)n_in; (void)out_size;
}

// round 8
// speedup vs baseline: 1.0597x; 1.0597x over previous
#include <cuda_runtime.h>
#include <cuda_bf16.h>
#include <mma.h>
#include <cstdint>

using namespace nvcuda;

#define Bd   32
#define Ld   64
#define Hd   512
#define WDd  300
#define Vd   32000
#define Td   48
#define KX   1324      // 512 + 300 + 512
#define KXP  1344      // padded to 64*21 (col 1324 = bias via x=1.0, rest 0)
#define KIH  812       // 512 + 300
#define G3   1536      // 3*H
#define KC   64        // GEMM k-chunk
#define NCH  (KXP / KC)   // 21

// split-K geometry
#define SHP  11
#define KCHP 48        // hidproj: 11*48 = 528 >= 512
#define SGH  4
#define KCGH 128       // gh: 4*128 = 512
#define NB_OUT 250     // 32000/128 gemm blocks
#define NB_HP  44      // hidproj: 4 n-blocks * 11 k-slots
#define NB_GH  48      // gh: 12 n-blocks * 4 k-slots

// ---------------- device scratch (static globals; no allocation) ----------------
__device__ __align__(256) __nv_bfloat16 g_Wb[(size_t)Vd * KXP];   // bf16 W_out (+bias col), ~86MB
__device__ __align__(16)  float g_WahT[Hd * Hd];                  // W_a_hid transposed [n][k]
__device__ __align__(16)  float g_encproj[Bd * Ld * Hd];          // enc @ W_a_enc
__device__ __align__(16)  float g_encW[Bd * Ld * G3];             // enc @ W_ih[:,:512]^T  (12.6MB)
__device__ __align__(16)  float g_gxe[Td * Bd * G3];              // emb_t @ W_ih[:,512:]^T (9.4MB)
__device__ __align__(16)  float g_emb[Td * Bd * WDd];
__device__ __align__(16)  float g_hid[2 * Bd * Hd];               // double buffer
__device__ __align__(16)  float g_ghp[SGH * Bd * G3];             // gh split-K partials
__device__ __align__(16)  float g_hpp[SHP * Bd * Hd];             // hidproj split-K partials
__device__ __align__(16)  float g_sc[Bd * Ld];                    // attention scores
__device__ __align__(16)  float g_obuf[Bd * Vd];                  // raw logits scratch (L2-hot)
__device__ __align__(256) __nv_bfloat16 g_xbf[Bd * KXP];          // bf16 [h_new|emb|hid_old|1|0..]

// ---------------- MUFU-free transcendentals (FMA/ALU pipes only) ----------------
__device__ __forceinline__ float fexp_neg(float x) {   // exp(x), x<=0; rel err ~2e-6
    x = fmaxf(x, -87.0f);
    float y = x * 1.44269504088896f;
    float n = rintf(y);
    float f = y - n;
    float p = 1.33335581e-3f;
    p = fmaf(p, f, 9.61812910e-3f);
    p = fmaf(p, f, 5.55041086e-2f);
    p = fmaf(p, f, 2.40226512e-1f);
    p = fmaf(p, f, 6.93147182e-1f);
    p = fmaf(p, f, 1.0f);
    return __int_as_float(((int)n + 127) << 23) * p;
}
__device__ __forceinline__ float frcp12(float d) {     // 1/d, d in [1,2]
    float r = fmaf(-0.5f, d, 1.45710678f);
    r = r * fmaf(-d, r, 2.0f);
    r = r * fmaf(-d, r, 2.0f);
    r = r * fmaf(-d, r, 2.0f);
    return r;
}
__device__ __forceinline__ float ftanh(float x) {
    float ax = fminf(fabsf(x), 9.0f);
    float z = fexp_neg(-2.0f * ax);
    float r = frcp12(1.0f + z);
    float t = fmaf(-2.0f * z, r, 1.0f);
    return copysignf(t, x);
}
__device__ __forceinline__ float fsigm(float x) {
    float ax = fminf(fabsf(x), 30.0f);
    float z = fexp_neg(-ax);
    float r = frcp12(1.0f + z);
    return (x >= 0.f) ? r : z * r;
}

// ---------------- precompute kernels ----------------
__global__ void k_zero_tail(float* __restrict__ out) {
    size_t base = (size_t)Td * Bd * Vd;
    size_t n = (size_t)(Ld - Td) * Bd * Vd;
    size_t i = (size_t)blockIdx.x * blockDim.x + threadIdx.x;
    if (i < n) out[base + i] = 0.f;
}

__global__ void k_convW(const float* __restrict__ W, const float* __restrict__ bout) {
    unsigned i = blockIdx.x * blockDim.x + threadIdx.x;
    unsigned total = (unsigned)Vd * KXP;
    if (i >= total) return;
    unsigned n = i / KXP;
    unsigned k = i - n * KXP;
    float v = (k < KX) ? W[(size_t)n * KX + k] : (k == KX ? bout[n] : 0.f);
    g_Wb[i] = __float2bfloat16(v);
}

// static part of x: bias col = 1, pad cols = 0
__global__ void k_init_xbf() {
    int b = threadIdx.x >> 5;       // 0..31 (1024 threads: 32 warps)
    int j = threadIdx.x & 31;
    if (b < Bd && KX + j < KXP)
        g_xbf[b * KXP + KX + j] = __float2bfloat16(j == 0 ? 1.0f : 0.0f);
}

__global__ void k_transpWah(const float* __restrict__ W_attn) {
    unsigned i = blockIdx.x * blockDim.x + threadIdx.x;
    if (i >= Hd * Hd) return;
    unsigned n = i / Hd, k = i - n * Hd;
    g_WahT[n * Hd + k] = W_attn[(size_t)(Hd + k) * Hd + n];
}

__global__ void k_gather_emb(const int* __restrict__ targets, const float* __restrict__ embed) {
    unsigned i = blockIdx.x * blockDim.x + threadIdx.x;
    unsigned total = Td * Bd * WDd;
    if (i >= total) return;
    unsigned t = i / (Bd * WDd);
    unsigned r = i - t * (Bd * WDd);
    unsigned b = r / WDd;
    unsigned j = r - b * WDd;
    int tok = (t == 0) ? 1 : targets[b * Td + (t - 1)];
    g_emb[i] = embed[(size_t)tok * WDd + j];
}

__global__ void k_init_hid(const float* __restrict__ ctxv) {
    int i = blockIdx.x * blockDim.x + threadIdx.x;
    if (i < Bd * Hd) g_hid[i] = ctxv[i];
}

__global__ void k_copy_hfinal(float* __restrict__ out) {
    int i = blockIdx.x * blockDim.x + threadIdx.x;
    if (i < Bd * Hd) out[(size_t)Ld * Bd * Vd + i] = g_hid[i];  // h_final in buffer 0
}

// enc_proj = enc(2048x512) @ W_a_enc, element (k,n) of W at W_attn[k*512+n]
__global__ void __launch_bounds__(256) k_encproj(const float* __restrict__ A,
                                                 const float* __restrict__ W_attn)
{
    __shared__ float As[32][33];
    __shared__ float Bs[64][33];
    int tid = threadIdx.x;
    int m0 = blockIdx.y * 32;
    int n0 = blockIdx.x * 64;
    int tm = tid >> 4, tn = tid & 15;
    float acc[2][4];
#pragma unroll
    for (int i = 0; i < 2; i++)
#pragma unroll
        for (int j = 0; j < 4; j++) acc[i][j] = 0.f;

    for (int k0 = 0; k0 < Hd; k0 += 32) {
        {
            int m = tid >> 3, kk = (tid & 7) << 2;
            float4 v = *(const float4*)(A + (size_t)(m0 + m) * Hd + k0 + kk);
            As[m][kk] = v.x; As[m][kk + 1] = v.y; As[m][kk + 2] = v.z; As[m][kk + 3] = v.w;
        }
#pragma unroll
        for (int i = 0; i < 8; i++) {
            int idx = tid + i * 256;
            int kk = idx >> 6;
            int n  = idx & 63;
            Bs[n][kk] = W_attn[(size_t)(k0 + kk) * Hd + n0 + n];
        }
        __syncthreads();
#pragma unroll
        for (int kk = 0; kk < 32; kk++) {
            float a0 = As[tm * 2][kk], a1 = As[tm * 2 + 1][kk];
            float b0 = Bs[tn * 4][kk], b1 = Bs[tn * 4 + 1][kk];
            float b2 = Bs[tn * 4 + 2][kk], b3 = Bs[tn * 4 + 3][kk];
            acc[0][0] += a0 * b0; acc[0][1] += a0 * b1; acc[0][2] += a0 * b2; acc[0][3] += a0 * b3;
            acc[1][0] += a1 * b0; acc[1][1] += a1 * b1; acc[1][2] += a1 * b2; acc[1][3] += a1 * b3;
        }
        __syncthreads();
    }
#pragma unroll
    for (int i = 0; i < 2; i++) {
        int m = m0 + tm * 2 + i;
#pragma unroll
        for (int j = 0; j < 4; j++)
            g_encproj[(size_t)m * Hd + n0 + tn * 4 + j] = acc[i][j];
    }
}

// ---------------- generic SGEMM C[m][n] = sum_k A[m][k]*B[n*ldb+k], 32x64 tiles, K-guarded ----------------
__global__ void __launch_bounds__(256) sgemm_abt(
    const float* __restrict__ A, int lda,
    const float* __restrict__ B, int ldb,
    float* __restrict__ C, int ldc, int K)
{
    __shared__ float As[32][33];
    __shared__ float Bs[64][33];
    int tid = threadIdx.x;
    int m0 = blockIdx.y * 32;
    int n0 = blockIdx.x * 64;
    int tm = tid >> 4, tn = tid & 15;
    float acc[2][4];
#pragma unroll
    for (int i = 0; i < 2; i++)
#pragma unroll
        for (int j = 0; j < 4; j++) acc[i][j] = 0.f;

    for (int k0 = 0; k0 < K; k0 += 32) {
        {
            int m = tid >> 3, kk = (tid & 7) << 2;
            float4 v = make_float4(0.f, 0.f, 0.f, 0.f);
            if (k0 + kk < K)
                v = *(const float4*)(A + (size_t)(m0 + m) * lda + k0 + kk);
            As[m][kk] = v.x; As[m][kk + 1] = v.y; As[m][kk + 2] = v.z; As[m][kk + 3] = v.w;
        }
#pragma unroll
        for (int i = 0; i < 2; i++) {
            int idx = tid + i * 256;
            int n   = idx >> 3;
            int kk  = (idx & 7) << 2;
            float4 v = make_float4(0.f, 0.f, 0.f, 0.f);
            if (k0 + kk < K)
                v = *(const float4*)(B + (size_t)(n0 + n) * ldb + k0 + kk);
            Bs[n][kk] = v.x; Bs[n][kk + 1] = v.y; Bs[n][kk + 2] = v.z; Bs[n][kk + 3] = v.w;
        }
        __syncthreads();
#pragma unroll
        for (int kk = 0; kk < 32; kk++) {
            float a0 = As[tm * 2][kk], a1 = As[tm * 2 + 1][kk];
            float b0 = Bs[tn * 4][kk], b1 = Bs[tn * 4 + 1][kk];
            float b2 = Bs[tn * 4 + 2][kk], b3 = Bs[tn * 4 + 3][kk];
            acc[0][0] += a0 * b0; acc[0][1] += a0 * b1; acc[0][2] += a0 * b2; acc[0][3] += a0 * b3;
            acc[1][0] += a1 * b0; acc[1][1] += a1 * b1; acc[1][2] += a1 * b2; acc[1][3] += a1 * b3;
        }
        __syncthreads();
    }
#pragma unroll
    for (int i = 0; i < 2; i++) {
        int m = m0 + tm * 2 + i;
#pragma unroll
        for (int j = 0; j < 4; j++)
            C[(size_t)m * ldc + n0 + tn * 4 + j] = acc[i][j];
    }
}

// ---------------- M=32 split-K GEMM tile (used for hidproj + gh partials) ----------------
__device__ __forceinline__ void mm32_tile(
    const float* __restrict__ A, int lda,
    const float* __restrict__ B, int ldb,
    int k_beg, int k_end, int n0,
    float* __restrict__ C, int ldc)
{
    __shared__ float As[32][9];
    __shared__ float Bs[8][132];
    int tid = threadIdx.x;
    int tm = tid >> 5;
    int tn = tid & 31;
    float acc[4][4];
#pragma unroll
    for (int i = 0; i < 4; i++)
#pragma unroll
        for (int j = 0; j < 4; j++) acc[i][j] = 0.f;

    for (int k0 = k_beg; k0 < k_end; k0 += 8) {
        {
            int m = tid >> 3, kk = tid & 7;
            int k = k0 + kk;
            As[m][kk] = (k < k_end) ? A[(size_t)m * lda + k] : 0.f;
        }
#pragma unroll
        for (int r = 0; r < 4; r++) {
            int idx = tid + r * 256;
            int n = idx >> 3, kk = idx & 7;
            int k = k0 + kk;
            Bs[kk][n] = (k < k_end) ? B[(size_t)(n0 + n) * ldb + k] : 0.f;
        }
        __syncthreads();
#pragma unroll
        for (int kk = 0; kk < 8; kk++) {
            float a0 = As[tm * 4][kk];
            float a1 = As[tm * 4 + 1][kk];
            float a2 = As[tm * 4 + 2][kk];
            float a3 = As[tm * 4 + 3][kk];
            float4 b = *(const float4*)&Bs[kk][tn * 4];
            acc[0][0] += a0 * b.x; acc[0][1] += a0 * b.y; acc[0][2] += a0 * b.z; acc[0][3] += a0 * b.w;
            acc[1][0] += a1 * b.x; acc[1][1] += a1 * b.y; acc[1][2] += a1 * b.z; acc[1][3] += a1 * b.w;
            acc[2][0] += a2 * b.x; acc[2][1] += a2 * b.y; acc[2][2] += a2 * b.z; acc[2][3] += a2 * b.w;
            acc[3][0] += a3 * b.x; acc[3][1] += a3 * b.y; acc[3][2] += a3 * b.z; acc[3][3] += a3 * b.w;
        }
        __syncthreads();
    }
#pragma unroll
    for (int i = 0; i < 4; i++) {
        float4 v = make_float4(acc[i][0], acc[i][1], acc[i][2], acc[i][3]);
        *(float4*)&C[(size_t)(tm * 4 + i) * ldc + n0 + tn * 4] = v;
    }
}

// hidproj partials: h @ W_a_hid^T  (44 blocks)
__device__ __forceinline__ void hp_block(int e, const float* __restrict__ h) {
    int nbi = e & 3;
    int s = e >> 2;
    int kb = s * KCHP;
    int ke = min(kb + KCHP, Hd);
    mm32_tile(h, Hd, g_WahT, Hd, kb, ke, nbi * 128,
              g_hpp + (size_t)s * Bd * Hd, Hd);
}

// gh partials: h @ W_hh^T  (48 blocks)
__device__ __forceinline__ void gh_block(int e, const float* __restrict__ h,
                                         const float* __restrict__ W_hh) {
    int nbi = e % 12;
    int s = e / 12;
    int kb = s * KCGH;
    mm32_tile(h, Hd, W_hh, Hd, kb, kb + KCGH, nbi * 128,
              g_ghp + (size_t)s * Bd * G3, G3);
}

// prologue: hidproj + gh partials of h0 (92 blocks)
__global__ void __launch_bounds__(256) k_prep0(const float* __restrict__ W_hh) {
    if (blockIdx.x < NB_HP) hp_block(blockIdx.x, g_hid);
    else                    gh_block(blockIdx.x - NB_HP, g_hid, W_hh);
}

// ---------------- attention scores block: 16 l-rows for batch b ----------------
__device__ __forceinline__ void sc_block(int b, int l0,
                                         const float* __restrict__ v_energy,
                                         const float* __restrict__ b_attn)
{
    int tid = threadIdx.x;
    __shared__ float s_hp[Hd];
    __shared__ float s_v[Hd];

    for (int i = tid; i < Hd; i += 256) {
        float hp = b_attn[i];
#pragma unroll
        for (int s = 0; s < SHP; s++) hp += g_hpp[(size_t)s * Bd * Hd + b * Hd + i];
        s_hp[i] = hp;
        s_v[i]  = v_energy[i];
    }
    __syncthreads();

    int w = tid >> 5, lane = tid & 31;
#pragma unroll
    for (int i = 0; i < 2; i++) {
        int l = l0 + w * 2 + i;
        const float* ep = g_encproj + (size_t)(b * Ld + l) * Hd;
        float acc = 0.f;
#pragma unroll 4
        for (int j = lane; j < Hd; j += 32)
            acc += ftanh(ep[j] + s_hp[j]) * s_v[j];
#pragma unroll
        for (int off = 16; off; off >>= 1)
            acc += __shfl_down_sync(0xffffffffu, acc, off);
        if (lane == 0) g_sc[b * Ld + l] = acc;
    }
}

// prologue scores for t=0
__global__ void __launch_bounds__(256) k_attn_sc(const float* __restrict__ v_energy,
                                                 const float* __restrict__ b_attn)
{
    sc_block(blockIdx.x, blockIdx.y * 16, v_energy, b_attn);
}

// ---------------- fused per-step: softmax -> gx_ctx -> GRU gates -> h_new + bf16 x ----------------
__global__ void __launch_bounds__(512) k_step(const float* __restrict__ b_ih,
                                              const float* __restrict__ b_hh,
                                              int t, int cur)
{
    int b = blockIdx.x;
    int tid = threadIdx.x;
    __shared__ float s_sc[Ld];
    __shared__ float s_w[Ld];

    if (tid < Ld) s_sc[tid] = g_sc[b * Ld + tid];
    __syncthreads();
    if (tid < Ld) {
        float m = -1e30f;
#pragma unroll
        for (int l = 0; l < Ld; l++) m = fmaxf(m, s_sc[l]);
        float Z = 0.f;
#pragma unroll
        for (int l = 0; l < Ld; l++) Z += fexp_neg(s_sc[l] - m);
        s_w[tid] = fexp_neg(s_sc[tid] - m) / Z;
    }
    __syncthreads();

    // gx_ctx for the 3 gates of dim tid: n = tid, 512+tid, 1024+tid
    float gxc0 = 0.f, gxc1 = 0.f, gxc2 = 0.f;
    const float* ew = g_encW + (size_t)b * Ld * G3 + tid;
#pragma unroll 4
    for (int l = 0; l < Ld; l++) {
        float wl = s_w[l];
        gxc0 = fmaf(wl, ew[0],      gxc0);
        gxc1 = fmaf(wl, ew[Hd],     gxc1);
        gxc2 = fmaf(wl, ew[2 * Hd], gxc2);
        ew += G3;
    }

    int i = tid;
    const float* ge = g_gxe + (size_t)(t * Bd + b) * G3;
    float gxr = gxc0 + ge[i]          + b_ih[i];
    float gxz = gxc1 + ge[Hd + i]     + b_ih[Hd + i];
    float gxn = gxc2 + ge[2 * Hd + i] + b_ih[2 * Hd + i];

    float ghr = b_hh[i], ghz = b_hh[Hd + i], ghn = b_hh[2 * Hd + i];
#pragma unroll
    for (int s = 0; s < SGH; s++) {
        const float* p = g_ghp + (size_t)s * Bd * G3 + b * G3;
        ghr += p[i]; ghz += p[Hd + i]; ghn += p[2 * Hd + i];
    }

    float r = fsigm(gxr + ghr);
    float z = fsigm(gxz + ghz);
    float n = ftanh(gxn + r * ghn);
    const float* hin = g_hid + cur * (Bd * Hd);
    float* hout      = g_hid + (1 - cur) * (Bd * Hd);
    float ho = hin[b * Hd + i];
    float hn = (1.f - z) * n + z * ho;

    hout[b * Hd + i] = hn;
    g_xbf[b * KXP + i]       = __float2bfloat16(hn);
    g_xbf[b * KXP + KIH + i] = __float2bfloat16(ho);
    if (i < WDd)
        g_xbf[b * KXP + Hd + i] = __float2bfloat16(g_emb[(size_t)(t * Bd + b) * WDd + i]);
}

// ---------------- output GEMM: smem-staged bf16 wmma + hidproj/gh partials of h_{t+1} ----------------
// 32x128 C tile per block; B chunk staged in smem via coalesced float4 loads, wmma via LDSM.
__global__ void __launch_bounds__(256) k_out_hp(int cur, const float* __restrict__ W_hh)
{
    if (blockIdx.x < NB_OUT) {
        __shared__ __nv_bfloat16 As[32][KC + 8];
        __shared__ __nv_bfloat16 Bs[128][KC + 8];
        int tid = threadIdx.x;
        int n0 = blockIdx.x * 128;
        int warp = tid >> 5;                  // 0..7 -> 16-col strip

        wmma::fragment<wmma::accumulator, 16, 16, 16, float> acc0, acc1;
        wmma::fill_fragment(acc0, 0.f);
        wmma::fill_fragment(acc1, 0.f);

        for (int kc = 0; kc < NCH; kc++) {
            {   // A chunk: 32 rows x 64 k = 256 float4 (1 per thread)
                int row = tid >> 3, slot = tid & 7;
                *(float4*)&As[row][slot * 8] =
                    *(const float4*)(g_xbf + (size_t)row * KXP + kc * KC + slot * 8);
            }
#pragma unroll
            for (int r = 0; r < 4; r++) {   // B chunk: 128 rows x 64 k = 1024 float4
                int idx = tid + r * 256;
                int row = idx >> 3, slot = idx & 7;
                *(float4*)&Bs[row][slot * 8] =
                    *(const float4*)(g_Wb + (size_t)(n0 + row) * KXP + kc * KC + slot * 8);
            }
            __syncthreads();
#pragma unroll
            for (int kk = 0; kk < KC / 16; kk++) {
                wmma::fragment<wmma::matrix_b, 16, 16, 16, __nv_bfloat16, wmma::col_major> b;
                wmma::load_matrix_sync(b, &Bs[warp * 16][kk * 16], KC + 8);
                wmma::fragment<wmma::matrix_a, 16, 16, 16, __nv_bfloat16, wmma::row_major> a0, a1;
                wmma::load_matrix_sync(a0, &As[0][kk * 16],  KC + 8);
                wmma::load_matrix_sync(a1, &As[16][kk * 16], KC + 8);
                wmma::mma_sync(acc0, a0, b, acc0);
                wmma::mma_sync(acc1, a1, b, acc1);
            }
            __syncthreads();
        }
        float* cp = g_obuf + n0 + warp * 16;
        wmma::store_matrix_sync(cp,                   acc0, Vd, wmma::mem_row_major);
        wmma::store_matrix_sync(cp + (size_t)16 * Vd, acc1, Vd, wmma::mem_row_major);
    } else if (blockIdx.x < NB_OUT + NB_HP) {
        hp_block(blockIdx.x - NB_OUT, g_hid + (1 - cur) * (Bd * Hd));
    } else {
        gh_block(blockIdx.x - NB_OUT - NB_HP, g_hid + (1 - cur) * (Bd * Hd), W_hh);
    }
}

// ---------------- fused: lse+write(t) || scores(t+1) ----------------
__global__ void __launch_bounds__(256) k_lse_sc(float* __restrict__ out, int t,
                                                const float* __restrict__ v_energy,
                                                const float* __restrict__ b_attn)
{
    if (blockIdx.x >= Bd) {
        int e = blockIdx.x - Bd;
        sc_block(e >> 2, (e & 3) * 16, v_energy, b_attn);
        return;
    }
    int b = blockIdx.x;
    int tid = threadIdx.x;
    const float* row = g_obuf + (size_t)b * Vd;
    float* orow = out + ((size_t)t * Bd + b) * Vd;
    __shared__ float sm[256], ss[256];

    // online max+sumexp in one deterministic pass
    float m = -1e30f, s = 0.f;
    for (int v = tid; v < Vd; v += 256) {
        float x = row[v];
        if (x > m) { s = fmaf(s, fexp_neg(m - x), 1.f); m = x; }
        else       { s += fexp_neg(x - m); }
    }
    sm[tid] = m; ss[tid] = s;
    __syncthreads();
    for (int off = 128; off; off >>= 1) {
        if (tid < off) {
            float m2 = sm[tid + off], s2 = ss[tid + off];
            float M = fmaxf(sm[tid], m2);
            ss[tid] = ss[tid] * fexp_neg(sm[tid] - M) + s2 * fexp_neg(m2 - M);
            sm[tid] = M;
        }
        __syncthreads();
    }
    float lse = sm[0] + logf(ss[0]);

    for (int v = tid; v < Vd; v += 256)
        orow[v] = row[v] - lse;
}

// ---------------- host launcher (graph-capturable; all default-stream) ----------------
extern "C" void kernel_launch(void* const* d_in, const int* in_sizes, int n_in,
                              void* d_out, int out_size)
{
    const float* enc      = (const float*)d_in[0];
    const float* ctxv     = (const float*)d_in[1];
    const int*   targets  = (const int*)  d_in[2];
    const float* embed    = (const float*)d_in[3];
    const float* W_attn   = (const float*)d_in[4];
    const float* b_attn   = (const float*)d_in[5];
    const float* v_energy = (const float*)d_in[6];
    const float* W_ih     = (const float*)d_in[7];
    const float* W_hh     = (const float*)d_in[8];
    const float* b_ih     = (const float*)d_in[9];
    const float* b_hh     = (const float*)d_in[10];
    const float* W_out    = (const float*)d_in[11];
    const float* b_out    = (const float*)d_in[12];
    float* out = (float*)d_out;

    float *p_encW, *p_gxe, *p_emb;
    cudaGetSymbolAddress((void**)&p_encW, g_encW);
    cudaGetSymbolAddress((void**)&p_gxe,  g_gxe);
    cudaGetSymbolAddress((void**)&p_emb,  g_emb);

    // ---- precompute ----
    {
        size_t n = (size_t)(Ld - Td) * Bd * Vd;
        k_zero_tail<<<(unsigned)((n + 255) / 256), 256>>>(out);
    }
    {
        unsigned total = (unsigned)Vd * KXP;
        k_convW<<<(total + 255) / 256, 256>>>(W_out, b_out);
    }
    k_init_xbf<<<1, 1024>>>();
    k_transpWah<<<(Hd * Hd + 255) / 256, 256>>>(W_attn);
    {
        unsigned total = Td * Bd * WDd;
        k_gather_emb<<<(total + 255) / 256, 256>>>(targets, embed);
    }
    k_init_hid<<<(Bd * Hd + 255) / 256, 256>>>(ctxv);
    k_encproj<<<dim3(Hd / 64, (Bd * Ld) / 32), 256>>>(enc, W_attn);
    // encW = enc @ W_ih[:, :512]^T   (2048 x 1536, K=512)
    sgemm_abt<<<dim3(G3 / 64, (Bd * Ld) / 32), 256>>>(enc, Hd, W_ih, KIH, p_encW, G3, Hd);
    // gx_emb = emb_all @ W_ih[:, 512:812]^T   (1536 x 1536, K=300)
    sgemm_abt<<<dim3(G3 / 64, (Td * Bd) / 32), 256>>>(p_emb, WDd, W_ih + Hd, KIH, p_gxe, G3, WDd);
    k_prep0<<<NB_HP + NB_GH, 256>>>(W_hh);             // hidproj + gh partials of h0
    k_attn_sc<<<dim3(Bd, 4), 256>>>(v_energy, b_attn); // scores for t=0

    // ---- 48 decode steps, 3 launches each ----
    for (int t = 0; t < Td; t++) {
        int cur = t & 1;
        k_step<<<Bd, 512>>>(b_ih, b_hh, t, cur);
        k_out_hp<<<NB_OUT + NB_HP + NB_GH, 256>>>(cur, W_hh);
        k_lse_sc<<<Bd + Bd * 4, 256>>>(out, t, v_energy, b_attn);
    }

    k_copy_hfinal<<<(Bd * Hd + 255) / 256, 256>>>(out);
    (void)in_sizes; (void)n_in; (void)out_size;
}